// round 4
// baseline (speedup 1.0000x reference)
#include <cuda_runtime.h>
#include <cstdint>
#include <cstddef>

#define TSTEPS 512
#define BATCH  128

// 192MB scratch for the input projection (static device array: allowed).
__device__ float g_Gx[(size_t)BATCH * TSTEPS * 768];

// ---- f32x2 helpers ----
typedef unsigned long long ull;
__device__ __forceinline__ ull pack2(float x, float y) {
    ull u; asm("mov.b64 %0, {%1,%2};" : "=l"(u) : "f"(x), "f"(y)); return u;
}
__device__ __forceinline__ void unpack2(ull u, float& x, float& y) {
    asm("mov.b64 {%0,%1}, %2;" : "=f"(x), "=f"(y) : "l"(u));
}
__device__ __forceinline__ void fma2(ull& d, ull a, ull b) {
    asm("fma.rn.f32x2 %0, %1, %2, %0;" : "+l"(d) : "l"(a), "l"(b));
}
__device__ __forceinline__ ull add2(ull a, ull b) {
    ull d; asm("add.rn.f32x2 %0, %1, %2;" : "=l"(d) : "l"(a), "l"(b)); return d;
}

// ---- cluster / mbarrier helpers ----
__device__ __forceinline__ uint32_t smem_u32(const void* p) {
    uint32_t a;
    asm("{ .reg .u64 t; cvta.to.shared.u64 t, %1; cvt.u32.u64 %0, t; }" : "=r"(a) : "l"(p));
    return a;
}
__device__ __forceinline__ uint32_t mapa_rank(uint32_t addr, uint32_t rank) {
    uint32_t r; asm("mapa.shared::cluster.u32 %0, %1, %2;" : "=r"(r) : "r"(addr), "r"(rank));
    return r;
}
__device__ __forceinline__ void st_cluster_u64(uint32_t addr, ull v) {
    asm volatile("st.shared::cluster.b64 [%0], %1;" :: "r"(addr), "l"(v));
}
__device__ __forceinline__ void cluster_sync() {
    asm volatile("barrier.cluster.arrive.aligned;" ::: "memory");
    asm volatile("barrier.cluster.wait.aligned;" ::: "memory");
}
__device__ __forceinline__ uint32_t cluster_rank() {
    uint32_t r; asm("mov.u32 %0, %%cluster_ctarank;" : "=r"(r)); return r;
}
__device__ __forceinline__ void mbar_init(uint32_t addr, uint32_t count) {
    asm volatile("mbarrier.init.shared.b64 [%0], %1;" :: "r"(addr), "r"(count) : "memory");
}
__device__ __forceinline__ void mbar_arrive_remote(uint32_t addr) {
    asm volatile("mbarrier.arrive.release.cluster.shared::cluster.b64 _, [%0];"
                 :: "r"(addr) : "memory");
}
__device__ __forceinline__ void mbar_wait(uint32_t addr, uint32_t parity) {
    uint32_t done = 0;
    do {
        asm volatile("{\n\t.reg .pred p;\n\t"
            "mbarrier.try_wait.parity.acquire.cluster.shared::cta.b64 p, [%1], %2, 0x989680;\n\t"
            "selp.b32 %0, 1, 0, p;\n\t}"
            : "=r"(done) : "r"(addr), "r"(parity) : "memory");
    } while (!done);
}

// fast activations
__device__ __forceinline__ float fast_sigmoid(float x) {
    return __fdividef(1.0f, 1.0f + __expf(-x));
}
__device__ __forceinline__ float fast_tanh(float x) {
    return 2.0f * __fdividef(1.0f, 1.0f + __expf(-2.0f * x)) - 1.0f;
}

// ============================================================================
// Stage 1: Gx[m][gate*256+n] = x[m] @ W[:256] + b.  BM=128 BN=64 BK=16.
// ============================================================================
__global__ __launch_bounds__(256) void proj_kernel(
    const float* __restrict__ x,
    const float* __restrict__ Wr, const float* __restrict__ br,
    const float* __restrict__ Wz, const float* __restrict__ bz,
    const float* __restrict__ Wc, const float* __restrict__ bc)
{
    const int mTile = blockIdx.x, nTile = blockIdx.y;
    const int gate = nTile >> 2, nGateBase = (nTile & 3) * 64;
    const float* W    = (gate == 0) ? Wr : ((gate == 1) ? Wz : Wc);
    const float* bias = (gate == 0) ? br : ((gate == 1) ? bz : bc);

    __shared__ float As[16][132];
    __shared__ float Ws[16][64];

    const int tid = threadIdx.x;
    const int tx = tid & 15, ty = tid >> 4;
    const int mBase = mTile * 128;

    ull acc[4][4];
    #pragma unroll
    for (int i = 0; i < 4; i++)
        #pragma unroll
        for (int jj = 0; jj < 4; jj++) acc[i][jj] = 0ull;

    float bv[4];
    #pragma unroll
    for (int jj = 0; jj < 4; jj++) bv[jj] = bias[nGateBase + tx * 4 + jj];

    for (int k0 = 0; k0 < 256; k0 += 16) {
        __syncthreads();
        #pragma unroll
        for (int q = 0; q < 2; q++) {
            int idx = tid + q * 256, row = idx >> 2, c4 = idx & 3;
            float4 v = *reinterpret_cast<const float4*>(
                &x[(size_t)(mBase + row) * 256 + k0 + c4 * 4]);
            As[c4 * 4 + 0][row] = v.x; As[c4 * 4 + 1][row] = v.y;
            As[c4 * 4 + 2][row] = v.z; As[c4 * 4 + 3][row] = v.w;
        }
        {
            int k = tid >> 4, n4 = (tid & 15) * 4;
            *reinterpret_cast<float4*>(&Ws[k][n4]) =
                *reinterpret_cast<const float4*>(&W[(size_t)(k0 + k) * 256 + nGateBase + n4]);
        }
        __syncthreads();

        #pragma unroll
        for (int k = 0; k < 16; k++) {
            const ull* ap = reinterpret_cast<const ull*>(&As[k][ty * 8]);
            ull a0 = ap[0], a1 = ap[1], a2 = ap[2], a3 = ap[3];
            #pragma unroll
            for (int jj = 0; jj < 4; jj++) {
                float w = Ws[k][tx * 4 + jj];
                ull w2 = pack2(w, w);
                fma2(acc[0][jj], a0, w2); fma2(acc[1][jj], a1, w2);
                fma2(acc[2][jj], a2, w2); fma2(acc[3][jj], a3, w2);
            }
        }
    }

    const int nOut = gate * 256 + nGateBase + tx * 4;
    #pragma unroll
    for (int rp = 0; rp < 4; rp++) {
        float r0[4], r1[4];
        #pragma unroll
        for (int jj = 0; jj < 4; jj++) {
            unpack2(acc[rp][jj], r0[jj], r1[jj]);
            r0[jj] += bv[jj]; r1[jj] += bv[jj];
        }
        int m0 = mBase + ty * 8 + rp * 2;
        *reinterpret_cast<float4*>(&g_Gx[(size_t)m0 * 768 + nOut]) =
            make_float4(r0[0], r0[1], r0[2], r0[3]);
        *reinterpret_cast<float4*>(&g_Gx[(size_t)(m0 + 1) * 768 + nOut]) =
            make_float4(r1[0], r1[1], r1[2], r1[3]);
    }
}

// ============================================================================
// Stage 2: recurrence, two-group (rows 0-3 / 4-7) software pipeline with
// per-group DSMEM mbarrier sync. 16 clusters x 8 CTAs; CTA j owns cols
// [32j,32j+32) per gate; recurrent weights in registers.
// ============================================================================
struct __align__(16) RecSmem {
    float hTA[256][4];    // h rows 0..3, transposed [k][row]
    float hTB[256][4];    // h rows 4..7
    float rhTA[256][4];
    float rhTB[256][4];
    ull   zA[2][32];      // z gate row-pairs, group A
    ull   zB[2][32];
    ull   red1[8][2][64]; // phase1 partials [kg][rowpair][col]
    ull   red2[16][2][32];
    unsigned long long mbar[4];  // mA1, mB1, mA2, mB2
};
__shared__ RecSmem S;

__global__ __launch_bounds__(256, 1) __cluster_dims__(8, 1, 1)
void rec_kernel(const float* __restrict__ h0,
                const float* __restrict__ Wr,
                const float* __restrict__ Wz,
                const float* __restrict__ Wc,
                float* __restrict__ out)
{
    const int tid = threadIdx.x;
    const int j = (int)cluster_rank();
    const int b0 = (blockIdx.x >> 3) * 8;

    // roles
    const int cg1 = tid & 31, kg1 = tid >> 5;   // phase1 gemm: cols {2cg1,2cg1+1}, 32-k group
    const int cg2 = tid & 15, kg2 = tid >> 4;   // phase2 gemm: cols {2cg2,2cg2+1}, 16-k group
    const int e1c = tid & 63, e1rp = (tid >> 6) & 1;  // epi1 (tid<128)
    const int e2c = tid & 31, e2rp = (tid >> 5) & 1;  // epi2 (tid<64)

    // ---- register-resident weights ----
    float w1[32][2];
    {
        const float* Wsel = (cg1 < 16) ? Wr : Wz;
        const int colb = j * 32 + ((2 * cg1) & 31);
        #pragma unroll
        for (int kk = 0; kk < 32; kk++) {
            const float* row = &Wsel[(size_t)(256 + kg1 * 32 + kk) * 256 + colb];
            w1[kk][0] = row[0]; w1[kk][1] = row[1];
        }
    }
    float w2[16][2];
    {
        const int colb = j * 32 + 2 * cg2;
        #pragma unroll
        for (int kk = 0; kk < 16; kk++) {
            const float* row = &Wc[(size_t)(256 + kg2 * 16 + kk) * 256 + colb];
            w2[kk][0] = row[0]; w2[kk][1] = row[1];
        }
    }

    // ---- init h, mbarriers ----
    for (int idx = tid; idx < 1024; idx += 256) {   // 4 rows x 256 k per group
        int r = idx >> 8, k = idx & 255;
        S.hTA[k][r] = h0[(size_t)(b0 + r) * 256 + k];
        S.hTB[k][r] = h0[(size_t)(b0 + 4 + r) * 256 + k];
    }
    if (tid == 0) {
        #pragma unroll
        for (int c = 0; c < 4; c++)
            mbar_init(smem_u32(&S.mbar[c]), 8);
    }
    __syncthreads();
    cluster_sync();   // peers' mbar init + hT init visible before any remote op

    // ---- peer base addresses ----
    const uint32_t base = smem_u32(&S);
    uint32_t peer[8];
    #pragma unroll
    for (int rk = 0; rk < 8; rk++) peer[rk] = mapa_rank(base, (uint32_t)rk);
    const uint32_t off_rhA = smem_u32(&S.rhTA[0][0]) - base;
    const uint32_t off_rhB = smem_u32(&S.rhTB[0][0]) - base;
    const uint32_t off_hA  = smem_u32(&S.hTA[0][0]) - base;
    const uint32_t off_hB  = smem_u32(&S.hTB[0][0]) - base;
    const uint32_t mbar0   = smem_u32(&S.mbar[0]);

    // ---- Gx address bases (per-thread roles) ----
    const int g1 = (e1c < 32) ? 0 : 1;
    const size_t sA0 = (size_t)(b0 + 2 * e1rp)     * TSTEPS * 768 + g1 * 256 + j * 32 + (e1c & 31);
    const size_t sA1 = (size_t)(b0 + 2 * e1rp + 1) * TSTEPS * 768 + g1 * 256 + j * 32 + (e1c & 31);
    const size_t sB0 = sA0 + (size_t)4 * TSTEPS * 768;
    const size_t sB1 = sA1 + (size_t)4 * TSTEPS * 768;
    const size_t cA0 = (size_t)(b0 + 2 * e2rp)     * TSTEPS * 768 + 512 + j * 32 + e2c;
    const size_t cA1 = (size_t)(b0 + 2 * e2rp + 1) * TSTEPS * 768 + 512 + j * 32 + e2c;
    const size_t cB0 = cA0 + (size_t)4 * TSTEPS * 768;
    const size_t cB1 = cA1 + (size_t)4 * TSTEPS * 768;

    const int kb1 = kg1 * 32, kb2 = kg2 * 16;

    #pragma unroll 1
    for (int t = 0; t < TSTEPS; t++) {
        const uint32_t pw = (uint32_t)(t & 1);           // within-step parity (mA1,mB1)
        const uint32_t pp = (uint32_t)((t + 1) & 1);     // prev-step parity (mA2,mB2)

        // ======== chunk A1 ========
        if (t > 0) mbar_wait(mbar0 + 16, pp);            // hTA(t) ready

        // Gx loads for this step (latency hidden under A1 gemm)
        const size_t to = (size_t)t * 768;
        float gA0 = 0.f, gA1 = 0.f, gB0 = 0.f, gB1 = 0.f;
        float hA0 = 0.f, hA1 = 0.f, hB0 = 0.f, hB1 = 0.f;
        if (tid < 128) {
            gA0 = g_Gx[sA0 + to]; gA1 = g_Gx[sA1 + to];
            gB0 = g_Gx[sB0 + to]; gB1 = g_Gx[sB1 + to];
        }
        if (tid < 64) {
            hA0 = g_Gx[cA0 + to]; hA1 = g_Gx[cA1 + to];
            hB0 = g_Gx[cB0 + to]; hB1 = g_Gx[cB1 + to];
        }

        {   // gemm A1: hTA @ W_{r,z}
            ull a0 = 0, a1 = 0, a2 = 0, a3 = 0;
            #pragma unroll
            for (int kk = 0; kk < 32; kk++) {
                ulonglong2 hp = *reinterpret_cast<const ulonglong2*>(&S.hTA[kb1 + kk][0]);
                ull wa = pack2(w1[kk][0], w1[kk][0]);
                ull wb = pack2(w1[kk][1], w1[kk][1]);
                fma2(a0, hp.x, wa); fma2(a1, hp.y, wa);
                fma2(a2, hp.x, wb); fma2(a3, hp.y, wb);
            }
            ulonglong2 v0; v0.x = a0; v0.y = a2;
            ulonglong2 v1; v1.x = a1; v1.y = a3;
            *reinterpret_cast<ulonglong2*>(&S.red1[kg1][0][2 * cg1]) = v0;
            *reinterpret_cast<ulonglong2*>(&S.red1[kg1][1][2 * cg1]) = v1;
        }
        __syncthreads();
        if (tid < 128) {   // epi A1
            ull s = S.red1[0][e1rp][e1c];
            #pragma unroll
            for (int g = 1; g < 8; g++) s = add2(s, S.red1[g][e1rp][e1c]);
            float lo, hi; unpack2(s, lo, hi);
            float v0 = fast_sigmoid(lo + gA0), v1 = fast_sigmoid(hi + gA1);
            if (e1c < 32) {
                int k = j * 32 + e1c;
                ull h2 = *reinterpret_cast<const ull*>(&S.hTA[k][2 * e1rp]);
                float ha, hb; unpack2(h2, ha, hb);
                ull rh2 = pack2(v0 * ha, v1 * hb);
                uint32_t o = off_rhA + (uint32_t)((k * 4 + 2 * e1rp) * 4);
                #pragma unroll
                for (int rk = 0; rk < 8; rk++) st_cluster_u64(peer[rk] + o, rh2);
            } else {
                S.zA[e1rp][e1c - 32] = pack2(v0, v1);
            }
        }
        __syncthreads();
        if (tid < 8) mbar_arrive_remote(mapa_rank(mbar0 + 0, (uint32_t)tid));  // mA1

        // ======== chunk B1 ========
        if (t > 0) mbar_wait(mbar0 + 24, pp);            // hTB(t) ready
        {
            ull a0 = 0, a1 = 0, a2 = 0, a3 = 0;
            #pragma unroll
            for (int kk = 0; kk < 32; kk++) {
                ulonglong2 hp = *reinterpret_cast<const ulonglong2*>(&S.hTB[kb1 + kk][0]);
                ull wa = pack2(w1[kk][0], w1[kk][0]);
                ull wb = pack2(w1[kk][1], w1[kk][1]);
                fma2(a0, hp.x, wa); fma2(a1, hp.y, wa);
                fma2(a2, hp.x, wb); fma2(a3, hp.y, wb);
            }
            ulonglong2 v0; v0.x = a0; v0.y = a2;
            ulonglong2 v1; v1.x = a1; v1.y = a3;
            __syncthreads();   // A1-epi red1 reads done before overwrite
            *reinterpret_cast<ulonglong2*>(&S.red1[kg1][0][2 * cg1]) = v0;
            *reinterpret_cast<ulonglong2*>(&S.red1[kg1][1][2 * cg1]) = v1;
        }
        __syncthreads();
        if (tid < 128) {   // epi B1
            ull s = S.red1[0][e1rp][e1c];
            #pragma unroll
            for (int g = 1; g < 8; g++) s = add2(s, S.red1[g][e1rp][e1c]);
            float lo, hi; unpack2(s, lo, hi);
            float v0 = fast_sigmoid(lo + gB0), v1 = fast_sigmoid(hi + gB1);
            if (e1c < 32) {
                int k = j * 32 + e1c;
                ull h2 = *reinterpret_cast<const ull*>(&S.hTB[k][2 * e1rp]);
                float ha, hb; unpack2(h2, ha, hb);
                ull rh2 = pack2(v0 * ha, v1 * hb);
                uint32_t o = off_rhB + (uint32_t)((k * 4 + 2 * e1rp) * 4);
                #pragma unroll
                for (int rk = 0; rk < 8; rk++) st_cluster_u64(peer[rk] + o, rh2);
            } else {
                S.zB[e1rp][e1c - 32] = pack2(v0, v1);
            }
        }
        __syncthreads();
        if (tid < 8) mbar_arrive_remote(mapa_rank(mbar0 + 8, (uint32_t)tid));  // mB1

        // ======== chunk A2 ========
        mbar_wait(mbar0 + 0, pw);                        // rhTA complete
        {
            ull a0 = 0, a1 = 0, a2 = 0, a3 = 0;
            #pragma unroll
            for (int kk = 0; kk < 16; kk++) {
                ulonglong2 hp = *reinterpret_cast<const ulonglong2*>(&S.rhTA[kb2 + kk][0]);
                ull wa = pack2(w2[kk][0], w2[kk][0]);
                ull wb = pack2(w2[kk][1], w2[kk][1]);
                fma2(a0, hp.x, wa); fma2(a1, hp.y, wa);
                fma2(a2, hp.x, wb); fma2(a3, hp.y, wb);
            }
            ulonglong2 v0; v0.x = a0; v0.y = a2;
            ulonglong2 v1; v1.x = a1; v1.y = a3;
            *reinterpret_cast<ulonglong2*>(&S.red2[kg2][0][2 * cg2]) = v0;
            *reinterpret_cast<ulonglong2*>(&S.red2[kg2][1][2 * cg2]) = v1;
        }
        __syncthreads();
        if (tid < 64) {   // epi A2
            ull s = S.red2[0][e2rp][e2c];
            #pragma unroll
            for (int g = 1; g < 16; g++) s = add2(s, S.red2[g][e2rp][e2c]);
            float lo, hi; unpack2(s, lo, hi);
            float c0 = fast_tanh(lo + hA0), c1 = fast_tanh(hi + hA1);
            float z0, z1; unpack2(S.zA[e2rp][e2c], z0, z1);
            int k = j * 32 + e2c;
            ull h2 = *reinterpret_cast<const ull*>(&S.hTA[k][2 * e2rp]);
            float ha, hb; unpack2(h2, ha, hb);
            float hn0 = ha + z0 * (c0 - ha);
            float hn1 = hb + z1 * (c1 - hb);
            out[((size_t)(b0 + 2 * e2rp) * TSTEPS + t) * 256 + k] = hn0;
            out[((size_t)(b0 + 2 * e2rp + 1) * TSTEPS + t) * 256 + k] = hn1;
            ull hn2 = pack2(hn0, hn1);
            uint32_t o = off_hA + (uint32_t)((k * 4 + 2 * e2rp) * 4);
            #pragma unroll
            for (int rk = 0; rk < 8; rk++) st_cluster_u64(peer[rk] + o, hn2);
        }
        __syncthreads();
        if (tid < 8) mbar_arrive_remote(mapa_rank(mbar0 + 16, (uint32_t)tid)); // mA2

        // ======== chunk B2 ========
        mbar_wait(mbar0 + 8, pw);                        // rhTB complete
        {
            ull a0 = 0, a1 = 0, a2 = 0, a3 = 0;
            #pragma unroll
            for (int kk = 0; kk < 16; kk++) {
                ulonglong2 hp = *reinterpret_cast<const ulonglong2*>(&S.rhTB[kb2 + kk][0]);
                ull wa = pack2(w2[kk][0], w2[kk][0]);
                ull wb = pack2(w2[kk][1], w2[kk][1]);
                fma2(a0, hp.x, wa); fma2(a1, hp.y, wa);
                fma2(a2, hp.x, wb); fma2(a3, hp.y, wb);
            }
            ulonglong2 v0; v0.x = a0; v0.y = a2;
            ulonglong2 v1; v1.x = a1; v1.y = a3;
            __syncthreads();   // A2-epi red2 reads done before overwrite
            *reinterpret_cast<ulonglong2*>(&S.red2[kg2][0][2 * cg2]) = v0;
            *reinterpret_cast<ulonglong2*>(&S.red2[kg2][1][2 * cg2]) = v1;
        }
        __syncthreads();
        if (tid < 64) {   // epi B2
            ull s = S.red2[0][e2rp][e2c];
            #pragma unroll
            for (int g = 1; g < 16; g++) s = add2(s, S.red2[g][e2rp][e2c]);
            float lo, hi; unpack2(s, lo, hi);
            float c0 = fast_tanh(lo + hB0), c1 = fast_tanh(hi + hB1);
            float z0, z1; unpack2(S.zB[e2rp][e2c], z0, z1);
            int k = j * 32 + e2c;
            ull h2 = *reinterpret_cast<const ull*>(&S.hTB[k][2 * e2rp]);
            float ha, hb; unpack2(h2, ha, hb);
            float hn0 = ha + z0 * (c0 - ha);
            float hn1 = hb + z1 * (c1 - hb);
            out[((size_t)(b0 + 4 + 2 * e2rp) * TSTEPS + t) * 256 + k] = hn0;
            out[((size_t)(b0 + 5 + 2 * e2rp) * TSTEPS + t) * 256 + k] = hn1;
            ull hn2 = pack2(hn0, hn1);
            uint32_t o = off_hB + (uint32_t)((k * 4 + 2 * e2rp) * 4);
            #pragma unroll
            for (int rk = 0; rk < 8; rk++) st_cluster_u64(peer[rk] + o, hn2);
        }
        __syncthreads();
        if (tid < 8) mbar_arrive_remote(mapa_rank(mbar0 + 24, (uint32_t)tid)); // mB2
    }

    cluster_sync();   // no CTA exits while remote ops are in flight
}

extern "C" void kernel_launch(void* const* d_in, const int* in_sizes, int n_in,
                              void* d_out, int out_size) {
    const float* x  = (const float*)d_in[0];
    const float* h0 = (const float*)d_in[1];
    const float* Wr = (const float*)d_in[2];
    const float* br = (const float*)d_in[3];
    const float* Wz = (const float*)d_in[4];
    const float* bz = (const float*)d_in[5];
    const float* Wc = (const float*)d_in[6];
    const float* bc = (const float*)d_in[7];
    float* out = (float*)d_out;

    proj_kernel<<<dim3(512, 12), 256>>>(x, Wr, br, Wz, bz, Wc, bc);
    rec_kernel<<<128, 256>>>(h0, Wr, Wz, Wc, out);
}

// round 5
// speedup vs baseline: 1.7832x; 1.7832x over previous
#include <cuda_runtime.h>
#include <cstdint>
#include <cstddef>

#define TSTEPS 512
#define BATCH  128

// 192MB scratch for the input projection (static device array: allowed).
__device__ float g_Gx[(size_t)BATCH * TSTEPS * 768];

// ---- f32x2 helpers ----
typedef unsigned long long ull;
__device__ __forceinline__ ull pack2(float x, float y) {
    ull u; asm("mov.b64 %0, {%1,%2};" : "=l"(u) : "f"(x), "f"(y)); return u;
}
__device__ __forceinline__ void unpack2(ull u, float& x, float& y) {
    asm("mov.b64 {%0,%1}, %2;" : "=f"(x), "=f"(y) : "l"(u));
}
__device__ __forceinline__ void fma2(ull& d, ull a, ull b) {
    asm("fma.rn.f32x2 %0, %1, %2, %0;" : "+l"(d) : "l"(a), "l"(b));
}
__device__ __forceinline__ ull add2(ull a, ull b) {
    ull d; asm("add.rn.f32x2 %0, %1, %2;" : "=l"(d) : "l"(a), "l"(b)); return d;
}

// ---- cluster helpers ----
__device__ __forceinline__ uint32_t smem_u32(const void* p) {
    uint32_t a;
    asm("{ .reg .u64 t; cvta.to.shared.u64 t, %1; cvt.u32.u64 %0, t; }" : "=r"(a) : "l"(p));
    return a;
}
__device__ __forceinline__ uint32_t mapa_rank(uint32_t addr, uint32_t rank) {
    uint32_t r; asm("mapa.shared::cluster.u32 %0, %1, %2;" : "=r"(r) : "r"(addr), "r"(rank));
    return r;
}
__device__ __forceinline__ void st_cluster_u64(uint32_t addr, ull v) {
    asm volatile("st.shared::cluster.b64 [%0], %1;" :: "r"(addr), "l"(v));
}
__device__ __forceinline__ void cluster_sync() {
    asm volatile("barrier.cluster.arrive.aligned;" ::: "memory");
    asm volatile("barrier.cluster.wait.aligned;" ::: "memory");
}
__device__ __forceinline__ uint32_t cluster_rank() {
    uint32_t r; asm("mov.u32 %0, %%cluster_ctarank;" : "=r"(r)); return r;
}

// fast activations
__device__ __forceinline__ float fast_sigmoid(float x) {
    return __fdividef(1.0f, 1.0f + __expf(-x));
}
__device__ __forceinline__ float fast_tanh(float x) {
    return 2.0f * __fdividef(1.0f, 1.0f + __expf(-2.0f * x)) - 1.0f;
}

// ============================================================================
// Stage 1: Gx[m][gate*256+n] = x[m] @ W[:256] + b.  BM=128 BN=64 BK=16.
// ============================================================================
__global__ __launch_bounds__(256) void proj_kernel(
    const float* __restrict__ x,
    const float* __restrict__ Wr, const float* __restrict__ br,
    const float* __restrict__ Wz, const float* __restrict__ bz,
    const float* __restrict__ Wc, const float* __restrict__ bc)
{
    const int mTile = blockIdx.x, nTile = blockIdx.y;
    const int gate = nTile >> 2, nGateBase = (nTile & 3) * 64;
    const float* W    = (gate == 0) ? Wr : ((gate == 1) ? Wz : Wc);
    const float* bias = (gate == 0) ? br : ((gate == 1) ? bz : bc);

    __shared__ float As[16][132];
    __shared__ float Ws[16][64];

    const int tid = threadIdx.x;
    const int tx = tid & 15, ty = tid >> 4;
    const int mBase = mTile * 128;

    ull acc[4][4];
    #pragma unroll
    for (int i = 0; i < 4; i++)
        #pragma unroll
        for (int jj = 0; jj < 4; jj++) acc[i][jj] = 0ull;

    float bv[4];
    #pragma unroll
    for (int jj = 0; jj < 4; jj++) bv[jj] = bias[nGateBase + tx * 4 + jj];

    for (int k0 = 0; k0 < 256; k0 += 16) {
        __syncthreads();
        #pragma unroll
        for (int q = 0; q < 2; q++) {
            int idx = tid + q * 256, row = idx >> 2, c4 = idx & 3;
            float4 v = *reinterpret_cast<const float4*>(
                &x[(size_t)(mBase + row) * 256 + k0 + c4 * 4]);
            As[c4 * 4 + 0][row] = v.x; As[c4 * 4 + 1][row] = v.y;
            As[c4 * 4 + 2][row] = v.z; As[c4 * 4 + 3][row] = v.w;
        }
        {
            int k = tid >> 4, n4 = (tid & 15) * 4;
            *reinterpret_cast<float4*>(&Ws[k][n4]) =
                *reinterpret_cast<const float4*>(&W[(size_t)(k0 + k) * 256 + nGateBase + n4]);
        }
        __syncthreads();

        #pragma unroll
        for (int k = 0; k < 16; k++) {
            const ull* ap = reinterpret_cast<const ull*>(&As[k][ty * 8]);
            ull a0 = ap[0], a1 = ap[1], a2 = ap[2], a3 = ap[3];
            #pragma unroll
            for (int jj = 0; jj < 4; jj++) {
                float w = Ws[k][tx * 4 + jj];
                ull w2 = pack2(w, w);
                fma2(acc[0][jj], a0, w2); fma2(acc[1][jj], a1, w2);
                fma2(acc[2][jj], a2, w2); fma2(acc[3][jj], a3, w2);
            }
        }
    }

    const int nOut = gate * 256 + nGateBase + tx * 4;
    #pragma unroll
    for (int rp = 0; rp < 4; rp++) {
        float r0[4], r1[4];
        #pragma unroll
        for (int jj = 0; jj < 4; jj++) {
            unpack2(acc[rp][jj], r0[jj], r1[jj]);
            r0[jj] += bv[jj]; r1[jj] += bv[jj];
        }
        int m0 = mBase + ty * 8 + rp * 2;
        *reinterpret_cast<float4*>(&g_Gx[(size_t)m0 * 768 + nOut]) =
            make_float4(r0[0], r0[1], r0[2], r0[3]);
        *reinterpret_cast<float4*>(&g_Gx[(size_t)(m0 + 1) * 768 + nOut]) =
            make_float4(r1[0], r1[1], r1[2], r1[3]);
    }
}

// ============================================================================
// Stage 2: recurrence. 32 clusters x 8 CTAs, 4 batch rows/cluster, 2 CTAs/SM.
// CTA rank j owns cols [32j,32j+32) per gate. Phase-1 weights in registers,
// phase-2 weights (Wc) in SMEM. h / r*h exchanged via DSMEM b64 pushes.
// ============================================================================
struct __align__(16) RecSmem {
    float wcT[256][32];   // Wc h-part: [k][c] (c = local col)
    float hT[256][4];     // h transposed [k][row]; peers push h_new here
    float rhT[256][4];    // r*h transposed; peers push here
    ull   z2[2][32];      // z gate, row-pairs
    ull   red[1024];      // aliased: phase1 [8][2][64], phase2 [16][2][32]
};

__global__ __launch_bounds__(256, 2) __cluster_dims__(8, 1, 1)
void rec_kernel(const float* __restrict__ h0,
                const float* __restrict__ Wr,
                const float* __restrict__ Wz,
                const float* __restrict__ Wc,
                float* __restrict__ out)
{
    extern __shared__ char smem_raw[];
    RecSmem& S = *reinterpret_cast<RecSmem*>(smem_raw);

    const int tid = threadIdx.x;
    const int j = (int)cluster_rank();       // 0..7
    const int b0 = (blockIdx.x >> 3) * 4;    // first batch row of cluster

    // roles
    const int c1  = tid & 31, kg1 = tid >> 5;   // phase1: col-pair {2c1,2c1+1} of 64, 32-k group
    const int c2p = tid & 15, kg2 = tid >> 4;   // phase2: col-pair {2c2p,2c2p+1} of 32, 16-k group
    const int e1c = tid & 63, e1rp = (tid >> 6) & 1;  // epi1 (tid<128): col 0..63, row-pair
    const int e2c = tid & 31, e2rp = (tid >> 5) & 1;  // epi2 (tid<64): col 0..31, row-pair

    // ---- phase-1 weights in registers (2 cols x 32 k) ----
    float w1[32][2];
    {
        const float* Wsel = (c1 < 16) ? Wr : Wz;
        const int colb = j * 32 + ((2 * c1) & 31);
        #pragma unroll
        for (int kk = 0; kk < 32; kk++) {
            const float* row = &Wsel[(size_t)(256 + kg1 * 32 + kk) * 256 + colb];
            w1[kk][0] = row[0]; w1[kk][1] = row[1];
        }
    }

    // ---- SMEM init: Wc tile, h state ----
    for (int idx = tid; idx < 256 * 32; idx += 256) {
        int k = idx >> 5, c = idx & 31;
        S.wcT[k][c] = Wc[(size_t)(256 + k) * 256 + j * 32 + c];
    }
    for (int idx = tid; idx < 1024; idx += 256) {
        int k = idx >> 2, r = idx & 3;
        S.hT[k][r] = h0[(size_t)(b0 + r) * 256 + k];
    }
    __syncthreads();
    cluster_sync();   // peers' hT init visible before any remote op

    // ---- peer DSMEM addresses ----
    const uint32_t base = smem_u32(&S);
    uint32_t peer[8];
    #pragma unroll
    for (int rk = 0; rk < 8; rk++) peer[rk] = mapa_rank(base, (uint32_t)rk);
    const uint32_t off_rh = smem_u32(&S.rhT[0][0]) - base;
    const uint32_t off_h  = smem_u32(&S.hT[0][0]) - base;

    // ---- Gx address bases ----
    const int g1 = (e1c < 32) ? 0 : 1;
    const size_t s0 = (size_t)(b0 + 2 * e1rp) * TSTEPS * 768 + g1 * 256 + j * 32 + (e1c & 31);
    const size_t s1 = s0 + (size_t)TSTEPS * 768;
    const size_t q0 = (size_t)(b0 + 2 * e2rp) * TSTEPS * 768 + 512 + j * 32 + e2c;
    const size_t q1 = q0 + (size_t)TSTEPS * 768;

    const int kb1 = kg1 * 32, kb2 = kg2 * 16;

    #pragma unroll 1
    for (int t = 0; t < TSTEPS; t++) {
        // Gx loads for this step (latency hidden under GEMM1)
        const size_t to = (size_t)t * 768;
        float gA0 = 0.f, gA1 = 0.f, gC0 = 0.f, gC1 = 0.f;
        if (tid < 128) { gA0 = g_Gx[s0 + to]; gA1 = g_Gx[s1 + to]; }
        if (tid < 64)  { gC0 = g_Gx[q0 + to]; gC1 = g_Gx[q1 + to]; }

        // -- phase 1: h @ Wh_{r,z}; 2 cols x 4 rows, 32 k --
        {
            ull a0 = 0, a1 = 0, a2 = 0, a3 = 0;   // (col0,rp0)(col0,rp1)(col1,rp0)(col1,rp1)
            #pragma unroll
            for (int kk = 0; kk < 32; kk++) {
                ulonglong2 hp = *reinterpret_cast<const ulonglong2*>(&S.hT[kb1 + kk][0]);
                ull wa = pack2(w1[kk][0], w1[kk][0]);
                ull wb = pack2(w1[kk][1], w1[kk][1]);
                fma2(a0, hp.x, wa); fma2(a1, hp.y, wa);
                fma2(a2, hp.x, wb); fma2(a3, hp.y, wb);
            }
            // red1[kg1][rp][c] (c = 2c1 / 2c1+1)
            ulonglong2 v0; v0.x = a0; v0.y = a2;   // rp0: cols 2c1, 2c1+1
            ulonglong2 v1; v1.x = a1; v1.y = a3;   // rp1
            *reinterpret_cast<ulonglong2*>(&S.red[kg1 * 128 + 0 * 64 + 2 * c1]) = v0;
            *reinterpret_cast<ulonglong2*>(&S.red[kg1 * 128 + 1 * 64 + 2 * c1]) = v1;
        }
        __syncthreads();

        // -- epilogue 1: sigmoid gates; push r*h row-pairs to all peers --
        if (tid < 128) {
            ull s = S.red[e1rp * 64 + e1c];
            #pragma unroll
            for (int g = 1; g < 8; g++) s = add2(s, S.red[g * 128 + e1rp * 64 + e1c]);
            float lo, hi; unpack2(s, lo, hi);
            float v0 = fast_sigmoid(lo + gA0), v1 = fast_sigmoid(hi + gA1);
            if (e1c < 32) {
                int k = j * 32 + e1c;
                ull h2 = *reinterpret_cast<const ull*>(&S.hT[k][2 * e1rp]);
                float ha, hb; unpack2(h2, ha, hb);
                ull rh2 = pack2(v0 * ha, v1 * hb);
                uint32_t o = off_rh + (uint32_t)((k * 4 + 2 * e1rp) * 4);
                #pragma unroll
                for (int rk = 0; rk < 8; rk++) st_cluster_u64(peer[rk] + o, rh2);
            } else {
                S.z2[e1rp][e1c - 32] = pack2(v0, v1);
            }
        }
        cluster_sync();

        // -- phase 2: (r*h) @ Wh_c; 2 cols x 4 rows, 16 k (Wc from SMEM) --
        {
            ull a0 = 0, a1 = 0, a2 = 0, a3 = 0;
            #pragma unroll
            for (int kk = 0; kk < 16; kk++) {
                ulonglong2 hp = *reinterpret_cast<const ulonglong2*>(&S.rhT[kb2 + kk][0]);
                float2 w = *reinterpret_cast<const float2*>(&S.wcT[kb2 + kk][2 * c2p]);
                ull wa = pack2(w.x, w.x);
                ull wb = pack2(w.y, w.y);
                fma2(a0, hp.x, wa); fma2(a1, hp.y, wa);
                fma2(a2, hp.x, wb); fma2(a3, hp.y, wb);
            }
            ulonglong2 v0; v0.x = a0; v0.y = a2;
            ulonglong2 v1; v1.x = a1; v1.y = a3;
            __syncthreads();   // epi1 red reads done before alias overwrite
            *reinterpret_cast<ulonglong2*>(&S.red[kg2 * 64 + 0 * 32 + 2 * c2p]) = v0;
            *reinterpret_cast<ulonglong2*>(&S.red[kg2 * 64 + 1 * 32 + 2 * c2p]) = v1;
        }
        __syncthreads();

        // -- epilogue 2: candidate, h update, output, push h_new --
        if (tid < 64) {
            ull s = S.red[e2rp * 32 + e2c];
            #pragma unroll
            for (int g = 1; g < 16; g++) s = add2(s, S.red[g * 64 + e2rp * 32 + e2c]);
            float lo, hi; unpack2(s, lo, hi);
            float t0 = fast_tanh(lo + gC0), t1 = fast_tanh(hi + gC1);
            float z0, z1; unpack2(S.z2[e2rp][e2c], z0, z1);
            int k = j * 32 + e2c;
            ull h2 = *reinterpret_cast<const ull*>(&S.hT[k][2 * e2rp]);
            float ha, hb; unpack2(h2, ha, hb);
            float hn0 = ha + z0 * (t0 - ha);
            float hn1 = hb + z1 * (t1 - hb);
            out[((size_t)(b0 + 2 * e2rp) * TSTEPS + t) * 256 + k] = hn0;
            out[((size_t)(b0 + 2 * e2rp + 1) * TSTEPS + t) * 256 + k] = hn1;
            ull hn2 = pack2(hn0, hn1);
            uint32_t o = off_h + (uint32_t)((k * 4 + 2 * e2rp) * 4);
            #pragma unroll
            for (int rk = 0; rk < 8; rk++) st_cluster_u64(peer[rk] + o, hn2);
        }
        cluster_sync();
    }
}

extern "C" void kernel_launch(void* const* d_in, const int* in_sizes, int n_in,
                              void* d_out, int out_size) {
    const float* x  = (const float*)d_in[0];
    const float* h0 = (const float*)d_in[1];
    const float* Wr = (const float*)d_in[2];
    const float* br = (const float*)d_in[3];
    const float* Wz = (const float*)d_in[4];
    const float* bz = (const float*)d_in[5];
    const float* Wc = (const float*)d_in[6];
    const float* bc = (const float*)d_in[7];
    float* out = (float*)d_out;

    cudaFuncSetAttribute(rec_kernel, cudaFuncAttributeMaxDynamicSharedMemorySize,
                         (int)sizeof(RecSmem));

    proj_kernel<<<dim3(512, 12), 256>>>(x, Wr, br, Wz, bz, Wc, bc);
    rec_kernel<<<256, 256, sizeof(RecSmem)>>>(h0, Wr, Wz, Wc, out);
}